// round 10
// baseline (speedup 1.0000x reference)
#include <cuda_runtime.h>
#include <cuda_bf16.h>
#include <cstdint>
#include <math.h>

namespace {

constexpr int F = 3, B = 64, C = 16, D = 512;
constexpr int CD = C * D;                 // 8192
constexpr float EPSF = 1e-8f;
constexpr float NEGINF = -1e30f;
constexpr float INV_T = 10.0f;            // 1 / 0.1

// ---- device scratch (no allocation allowed) ----
__device__ __align__(16) __nv_bfloat16 g_bi[F * B * CD];   // bf16 fmaps_i
__device__ __align__(16) __nv_bfloat16 g_bj[F * B * CD];   // bf16 fmaps_j
__device__ float g_rni[F * B * C];        // per-channel ||.||^2 fmaps_i
__device__ float g_rnj[F * B * C];        // per-channel ||.||^2 fmaps_j
__device__ float g_an[F * B];             // anchor norms
__device__ float g_pos[F * B];            // pos_sim / T
__device__ float g_sim[2 * F * B * B];    // [type][f][i][j] logits
__device__ float g_loss[F * B];
__device__ int   g_done;                  // last-block counter (reset by k_prep)

__device__ __forceinline__ float warpsum(float v) {
#pragma unroll
    for (int o = 16; o; o >>= 1) v += __shfl_down_sync(0xffffffffu, v, o);
    return v;
}
__device__ __forceinline__ float warpmax(float v) {
#pragma unroll
    for (int o = 16; o; o >>= 1) v = fmaxf(v, __shfl_xor_sync(0xffffffffu, v, o));
    return v;
}

__device__ __forceinline__ uint32_t smem_u32(const void* p) {
    uint32_t a;
    asm("{ .reg .u64 t; cvta.to.shared.u64 t, %1; cvt.u32.u64 %0, t; }" : "=r"(a) : "l"(p));
    return a;
}
__device__ __forceinline__ void ldsm4(uint32_t* r, uint32_t addr) {
    asm volatile("ldmatrix.sync.aligned.m8n8.x4.shared.b16 {%0,%1,%2,%3}, [%4];"
        : "=r"(r[0]), "=r"(r[1]), "=r"(r[2]), "=r"(r[3]) : "r"(addr));
}
__device__ __forceinline__ void mma16816(float* c, const uint32_t* a,
                                         uint32_t b0, uint32_t b1) {
    asm volatile(
        "mma.sync.aligned.m16n8k16.row.col.f32.bf16.bf16.f32 "
        "{%0,%1,%2,%3}, {%4,%5,%6,%7}, {%8,%9}, {%0,%1,%2,%3};"
        : "+f"(c[0]), "+f"(c[1]), "+f"(c[2]), "+f"(c[3])
        : "r"(a[0]), "r"(a[1]), "r"(a[2]), "r"(a[3]), "r"(b0), "r"(b1));
}
__device__ __forceinline__ void cpasync16(uint32_t dst, const void* src) {
    asm volatile("cp.async.cg.shared.global [%0], [%1], 16;" :: "r"(dst), "l"(src));
}
#define CP_COMMIT() asm volatile("cp.async.commit_group;" ::: "memory")
#define CP_WAIT1() asm volatile("cp.async.wait_group 1;" ::: "memory")

// ---------------------------------------------------------------------------
// Kernel 1: fused prep — one pass over fp32 inputs, 1024 threads/block.
// Warp w handles half-channel (ch = w>>1, half = w&1).
// ---------------------------------------------------------------------------
__global__ void __launch_bounds__(1024) k_prep(const float* __restrict__ fi,
                                               const float* __restrict__ fj) {
    int fb = blockIdx.x;
    int t = threadIdx.x, w = t >> 5, lane = t & 31;
    if (fb == 0 && t == 0) g_done = 0;
    int ch = w >> 1, half = w & 1;
    const float4* ai = reinterpret_cast<const float4*>(fi + (size_t)fb * CD);
    const float4* aj = reinterpret_cast<const float4*>(fj + (size_t)fb * CD);
    __nv_bfloat162* bi = reinterpret_cast<__nv_bfloat162*>(g_bi + (size_t)fb * CD);
    __nv_bfloat162* bj = reinterpret_cast<__nv_bfloat162*>(g_bj + (size_t)fb * CD);

    __shared__ float sni[32], snj[32], sdot[32];

    float ssi = 0.f, ssj = 0.f, dot = 0.f;
#pragma unroll
    for (int q = 0; q < 2; q++) {
        int k = ch * 128 + half * 64 + q * 32 + lane;   // float4 index
        float4 vi = ai[k], vj = aj[k];
        ssi += vi.x * vi.x + vi.y * vi.y + vi.z * vi.z + vi.w * vi.w;
        ssj += vj.x * vj.x + vj.y * vj.y + vj.z * vj.z + vj.w * vj.w;
        dot += vi.x * vj.x + vi.y * vj.y + vi.z * vj.z + vi.w * vj.w;
        bi[2 * k]     = __floats2bfloat162_rn(vi.x, vi.y);
        bi[2 * k + 1] = __floats2bfloat162_rn(vi.z, vi.w);
        bj[2 * k]     = __floats2bfloat162_rn(vj.x, vj.y);
        bj[2 * k + 1] = __floats2bfloat162_rn(vj.z, vj.w);
    }
    ssi = warpsum(ssi);
    ssj = warpsum(ssj);
    dot = warpsum(dot);
    if (!lane) { sni[w] = ssi; snj[w] = ssj; sdot[w] = dot; }
    __syncthreads();
    if (t < C) {
        g_rni[fb * C + t] = sni[2 * t] + sni[2 * t + 1];
        g_rnj[fb * C + t] = snj[2 * t] + snj[2 * t + 1];
    }
    if (t == 0) {
        float na2 = 0.f, nb2 = 0.f, td = 0.f;
#pragma unroll
        for (int w2 = 0; w2 < 32; w2++) { na2 += sni[w2]; nb2 += snj[w2]; td += sdot[w2]; }
        float na = sqrtf(na2), nb = sqrtf(nb2);
        g_an[fb]  = na;
        g_pos[fb] = td / (fmaxf(na, EPSF) * fmaxf(nb, EPSF)) * INV_T;
    }
}

// ---------------------------------------------------------------------------
// Kernel 2: channel Gram via mma.sync (3-stage cp.async, K-slab 64) with a
// FUSED epilogue: the 128x128 fp32 tile goes to smem, and each 16x16
// sub-block yields one complete gathered-negative logit -> g_sim directly.
// No g_gram round trip. grid = 6*64 CTAs of 256 threads.
// ---------------------------------------------------------------------------
constexpr int KSLAB = 64;
constexpr int PITCH = 72;                    // halves per smem row (64 + 8 pad)
constexpr int TILE_BYTES = 128 * PITCH * 2;  // 18432 B
constexpr int STAGE_BYTES = 2 * TILE_BYTES;  // 36864 B (A + B)
constexpr int GRAM_SMEM = 3 * STAGE_BYTES;   // 110592 B
constexpr int EPITCH = 132;                  // fp32 epilogue pitch (128 + 4)

__global__ void __launch_bounds__(256, 2) k_gram_mma(const int* __restrict__ ids_raw,
                                                     const int* __restrict__ idxj,
                                                     const int* __restrict__ idxk) {
    extern __shared__ __align__(16) char smem[];
    uint32_t sb = smem_u32(smem);
    int tid = threadIdx.x, lane = tid & 31, warp = tid >> 5;
    int wm = warp & 1, wn = warp >> 1;     // 2 x 4 warp grid

    int bid = blockIdx.x;
    int g = bid >> 6;                      // 0..5 = f*2 + type
    int mi = (bid >> 3) & 7;
    int nj = bid & 7;
    int f = g >> 1, type = g & 1;

    const __nv_bfloat16* Asrc = g_bi + (size_t)f * B * CD + (size_t)mi * 128 * 512;
    const __nv_bfloat16* Bsrc = (type ? g_bi : g_bj) + (size_t)f * B * CD + (size_t)nj * 128 * 512;

    auto issue_slab = [&](int stage, int ks) {
        uint32_t s = sb + stage * STAGE_BYTES;
#pragma unroll
        for (int q = 0; q < 4; q++) {
            int idx = tid + q * 256;           // 0..1023
            int r = idx >> 3;                  // row 0..127
            int kc = (idx & 7) * 8;            // col halves 0..56
            cpasync16(s + (r * PITCH + kc) * 2, Asrc + (size_t)r * 512 + ks + kc);
            cpasync16(s + TILE_BYTES + (r * PITCH + kc) * 2,
                      Bsrc + (size_t)r * 512 + ks + kc);
        }
    };

    float acc[4][4][4];
#pragma unroll
    for (int a = 0; a < 4; a++)
#pragma unroll
        for (int b = 0; b < 4; b++)
#pragma unroll
            for (int q = 0; q < 4; q++) acc[a][b][q] = 0.f;

    issue_slab(0, 0);
    CP_COMMIT();
    issue_slab(1, KSLAB);
    CP_COMMIT();

    for (int s = 0; s < 8; s++) {
        CP_WAIT1();
        __syncthreads();
        if (s + 2 < 8) issue_slab((s + 2) % 3, (s + 2) * KSLAB);
        CP_COMMIT();                       // uniform group count (may be empty)

        uint32_t base = sb + (s % 3) * STAGE_BYTES;
#pragma unroll
        for (int kt = 0; kt < 4; kt++) {
            uint32_t af[4][4], bfr[2][4];
#pragma unroll
            for (int mt = 0; mt < 4; mt++) {
                int row = wm * 64 + mt * 16 + ((lane >> 3) & 1) * 8 + (lane & 7);
                int col = kt * 16 + (lane >> 4) * 8;
                ldsm4(af[mt], base + (row * PITCH + col) * 2);
            }
#pragma unroll
            for (int nt2 = 0; nt2 < 2; nt2++) {
                int nrow = wn * 32 + nt2 * 16 + (lane >> 4) * 8 + (lane & 7);
                int kcol = kt * 16 + ((lane >> 3) & 1) * 8;
                ldsm4(bfr[nt2], base + TILE_BYTES + (nrow * PITCH + kcol) * 2);
            }
#pragma unroll
            for (int mt = 0; mt < 4; mt++)
#pragma unroll
                for (int nt = 0; nt < 4; nt++)
                    mma16816(acc[mt][nt], af[mt],
                             bfr[nt >> 1][(nt & 1) * 2], bfr[nt >> 1][(nt & 1) * 2 + 1]);
        }
    }

    // ---- fused epilogue: tile -> smem fp32, then per-pair gathered sums ----
    __syncthreads();                       // all compute done; reuse pipeline smem
    float* sf = reinterpret_cast<float*>(smem);
    int gq = lane >> 2, tq = lane & 3;
#pragma unroll
    for (int mt = 0; mt < 4; mt++) {
#pragma unroll
        for (int nt = 0; nt < 4; nt++) {
            int m0 = wm * 64 + mt * 16 + gq;
            int n0 = wn * 32 + nt * 8 + tq * 2;
            *reinterpret_cast<float2*>(sf + m0 * EPITCH + n0) =
                make_float2(acc[mt][nt][0], acc[mt][nt][1]);
            *reinterpret_cast<float2*>(sf + (m0 + 8) * EPITCH + n0) =
                make_float2(acc[mt][nt][2], acc[mt][nt][3]);
        }
    }
    __syncthreads();

    bool is64 = (ids_raw[1] == 0) && (ids_raw[3] == 0) && (ids_raw[5] == 0) && (ids_raw[7] == 0);
    const long long* ids64 = reinterpret_cast<const long long*>(ids_raw);
    const int* idx = type ? idxk : idxj;
    const float* rn = type ? g_rni : g_rnj;

#pragma unroll
    for (int q = 0; q < 8; q++) {
        int p = warp * 8 + q;              // 0..63
        int il = p >> 3, jl = p & 7;
        int i = mi * 8 + il, j = nj * 8 + jl;
        float sacc = 0.f, nsq = 0.f;
        if (lane < 16) {
            int cc = idx[((size_t)((f * B + i) * B) + j) * C + lane];
            sacc = sf[(il * 16 + lane) * EPITCH + jl * 16 + cc];
            nsq  = rn[(f * B + j) * C + cc];
        }
#pragma unroll
        for (int o = 8; o; o >>= 1) {
            sacc += __shfl_down_sync(0xffffffffu, sacc, o);
            nsq  += __shfl_down_sync(0xffffffffu, nsq, o);
        }
        if (lane == 0) {
            long long myid = is64 ? ids64[i] : (long long)ids_raw[i];
            long long jid  = is64 ? ids64[j] : (long long)ids_raw[j];
            float na = fmaxf(g_an[f * B + i], EPSF);
            float nb = fmaxf(sqrtf(nsq), EPSF);
            bool valid = (j != i) && (jid != myid);
            g_sim[(size_t)type * F * B * B + (size_t)(f * B + i) * B + j] =
                valid ? (sacc / (na * nb) * INV_T) : NEGINF;
        }
    }
}

// ---------------------------------------------------------------------------
// Kernel 3: logsumexp (one warp per row) + last-block final sum.
// grid = 6 blocks of 1024 threads (32 warps -> 32 rows each).
// ---------------------------------------------------------------------------
__global__ void __launch_bounds__(1024) k_lse(float* __restrict__ out) {
    int t = threadIdx.x, w = t >> 5, lane = t & 31;
    int r = blockIdx.x * 32 + w;            // 0..191
    __shared__ float ssum[32];
    __shared__ int s_last;

    float p = g_pos[r];
    const float* sj = g_sim + (size_t)r * B;
    const float* sk = g_sim + (size_t)F * B * B + (size_t)r * B;
    float v0 = sj[lane], v1 = sj[lane + 32], v2 = sk[lane], v3 = sk[lane + 32];
    float m = fmaxf(fmaxf(v0, v1), fmaxf(v2, v3));
    m = fmaxf(m, p);
    m = warpmax(m);
    float s = expf(v0 - m) + expf(v1 - m) + expf(v2 - m) + expf(v3 - m);
    s = warpsum(s);
    if (!lane) {
        g_loss[r] = logf(s + expf(p - m)) + m - p;
        __threadfence();                    // release this row's result
    }
    __syncthreads();
    if (t == 0) {
        int done = atomicAdd(&g_done, 1);
        s_last = (done == 5) ? 1 : 0;
    }
    __syncthreads();

    if (s_last) {
        __threadfence();                    // acquire all g_loss writes
        float v = (t < F * B) ? g_loss[t] : 0.f;
        v = warpsum(v);
        if (!lane) ssum[w] = v;
        __syncthreads();
        if (t == 0) {
            float tot = 0.f;
#pragma unroll
            for (int w2 = 0; w2 < 32; w2++) tot += ssum[w2];
            out[0] = tot * (1.0f / 128.0f);   // / (2 * BATCH_SIZE)
        }
    }
}

}  // namespace

extern "C" void kernel_launch(void* const* d_in, const int* in_sizes, int n_in,
                              void* d_out, int out_size) {
    const float* fi   = (const float*)d_in[0];
    const float* fj   = (const float*)d_in[1];
    const int*   ids  = (const int*)d_in[2];
    const int*   idxj = (const int*)d_in[3];
    const int*   idxk = (const int*)d_in[4];
    float* out = (float*)d_out;

    static bool attr_done = false;
    if (!attr_done) {
        cudaFuncSetAttribute(k_gram_mma, cudaFuncAttributeMaxDynamicSharedMemorySize,
                             GRAM_SMEM);
        attr_done = true;
    }

    k_prep<<<F * B, 1024>>>(fi, fj);
    k_gram_mma<<<6 * 64, 256, GRAM_SMEM>>>(ids, idxj, idxk);
    k_lse<<<6, 1024>>>(out);
}

// round 12
// speedup vs baseline: 1.0484x; 1.0484x over previous
#include <cuda_runtime.h>
#include <cuda_bf16.h>
#include <cstdint>
#include <math.h>

namespace {

constexpr int F = 3, B = 64, C = 16, D = 512;
constexpr int CD = C * D;                 // 8192
constexpr float EPSF = 1e-8f;
constexpr float NEGINF = -1e30f;
constexpr float INV_T = 10.0f;            // 1 / 0.1

// ---- device scratch (no allocation allowed) ----
__device__ __align__(16) __nv_bfloat16 g_bi[F * B * CD];   // bf16 fmaps_i
__device__ __align__(16) __nv_bfloat16 g_bj[F * B * CD];   // bf16 fmaps_j
__device__ float g_rni[F * B * C];        // per-channel ||.||^2 fmaps_i
__device__ float g_rnj[F * B * C];        // per-channel ||.||^2 fmaps_j
__device__ float g_an[F * B];             // anchor norms
__device__ float g_pos[F * B];            // pos_sim / T
__device__ float g_sim[2 * F * B * B];    // [type][f][i][j] logits
__device__ float g_loss[F * B];
__device__ int   g_done;                  // last-block counter (reset by k_prep)

__device__ __forceinline__ float warpsum(float v) {
#pragma unroll
    for (int o = 16; o; o >>= 1) v += __shfl_down_sync(0xffffffffu, v, o);
    return v;
}
__device__ __forceinline__ float warpmax(float v) {
#pragma unroll
    for (int o = 16; o; o >>= 1) v = fmaxf(v, __shfl_xor_sync(0xffffffffu, v, o));
    return v;
}

__device__ __forceinline__ uint32_t smem_u32(const void* p) {
    uint32_t a;
    asm("{ .reg .u64 t; cvta.to.shared.u64 t, %1; cvt.u32.u64 %0, t; }" : "=r"(a) : "l"(p));
    return a;
}
__device__ __forceinline__ void ldsm4(uint32_t* r, uint32_t addr) {
    asm volatile("ldmatrix.sync.aligned.m8n8.x4.shared.b16 {%0,%1,%2,%3}, [%4];"
        : "=r"(r[0]), "=r"(r[1]), "=r"(r[2]), "=r"(r[3]) : "r"(addr));
}
__device__ __forceinline__ void mma16816(float* c, const uint32_t* a,
                                         uint32_t b0, uint32_t b1) {
    asm volatile(
        "mma.sync.aligned.m16n8k16.row.col.f32.bf16.bf16.f32 "
        "{%0,%1,%2,%3}, {%4,%5,%6,%7}, {%8,%9}, {%0,%1,%2,%3};"
        : "+f"(c[0]), "+f"(c[1]), "+f"(c[2]), "+f"(c[3])
        : "r"(a[0]), "r"(a[1]), "r"(a[2]), "r"(a[3]), "r"(b0), "r"(b1));
}
__device__ __forceinline__ void cpasync16(uint32_t dst, const void* src) {
    asm volatile("cp.async.cg.shared.global [%0], [%1], 16;" :: "r"(dst), "l"(src));
}
#define CP_COMMIT() asm volatile("cp.async.commit_group;" ::: "memory")
#define CP_WAIT1() asm volatile("cp.async.wait_group 1;" ::: "memory")

// ---------------------------------------------------------------------------
// Kernel 1: fused prep — one pass over fp32 inputs, 1024 threads/block.
// ---------------------------------------------------------------------------
__global__ void __launch_bounds__(1024) k_prep(const float* __restrict__ fi,
                                               const float* __restrict__ fj) {
    int fb = blockIdx.x;
    int t = threadIdx.x, w = t >> 5, lane = t & 31;
    if (fb == 0 && t == 0) g_done = 0;
    int ch = w >> 1, half = w & 1;
    const float4* ai = reinterpret_cast<const float4*>(fi + (size_t)fb * CD);
    const float4* aj = reinterpret_cast<const float4*>(fj + (size_t)fb * CD);
    __nv_bfloat162* bi = reinterpret_cast<__nv_bfloat162*>(g_bi + (size_t)fb * CD);
    __nv_bfloat162* bj = reinterpret_cast<__nv_bfloat162*>(g_bj + (size_t)fb * CD);

    __shared__ float sni[32], snj[32], sdot[32];

    float ssi = 0.f, ssj = 0.f, dot = 0.f;
#pragma unroll
    for (int q = 0; q < 2; q++) {
        int k = ch * 128 + half * 64 + q * 32 + lane;   // float4 index
        float4 vi = ai[k], vj = aj[k];
        ssi += vi.x * vi.x + vi.y * vi.y + vi.z * vi.z + vi.w * vi.w;
        ssj += vj.x * vj.x + vj.y * vj.y + vj.z * vj.z + vj.w * vj.w;
        dot += vi.x * vj.x + vi.y * vj.y + vi.z * vj.z + vi.w * vj.w;
        bi[2 * k]     = __floats2bfloat162_rn(vi.x, vi.y);
        bi[2 * k + 1] = __floats2bfloat162_rn(vi.z, vi.w);
        bj[2 * k]     = __floats2bfloat162_rn(vj.x, vj.y);
        bj[2 * k + 1] = __floats2bfloat162_rn(vj.z, vj.w);
    }
    ssi = warpsum(ssi);
    ssj = warpsum(ssj);
    dot = warpsum(dot);
    if (!lane) { sni[w] = ssi; snj[w] = ssj; sdot[w] = dot; }
    __syncthreads();
    if (t < C) {
        g_rni[fb * C + t] = sni[2 * t] + sni[2 * t + 1];
        g_rnj[fb * C + t] = snj[2 * t] + snj[2 * t + 1];
    }
    if (t == 0) {
        float na2 = 0.f, nb2 = 0.f, td = 0.f;
#pragma unroll
        for (int w2 = 0; w2 < 32; w2++) { na2 += sni[w2]; nb2 += snj[w2]; td += sdot[w2]; }
        float na = sqrtf(na2), nb = sqrtf(nb2);
        g_an[fb]  = na;
        g_pos[fb] = td / (fmaxf(na, EPSF) * fmaxf(nb, EPSF)) * INV_T;
    }
}

// ---------------------------------------------------------------------------
// Kernel 2: channel Gram via mma.sync (3-stage cp.async, K-slab 64) with a
// fused epilogue: 128x128 fp32 tile -> smem, each 16x16 sub-block yields one
// gathered-negative logit -> g_sim. Index/norm loads are BATCH-PREFETCHED
// (8-way MLP) and overlap the accumulator dump — the serial-idx-load latency
// that regressed R10 is removed.
// ---------------------------------------------------------------------------
constexpr int KSLAB = 64;
constexpr int PITCH = 72;                    // halves per smem row (64 + 8 pad)
constexpr int TILE_BYTES = 128 * PITCH * 2;  // 18432 B
constexpr int STAGE_BYTES = 2 * TILE_BYTES;  // 36864 B (A + B)
constexpr int GRAM_SMEM = 3 * STAGE_BYTES;   // 110592 B
constexpr int EPITCH = 132;                  // fp32 epilogue pitch (128 + 4)

__global__ void __launch_bounds__(256, 2) k_gram_mma(const int* __restrict__ ids_raw,
                                                     const int* __restrict__ idxj,
                                                     const int* __restrict__ idxk) {
    extern __shared__ __align__(16) char smem[];
    uint32_t sb = smem_u32(smem);
    int tid = threadIdx.x, lane = tid & 31, warp = tid >> 5;
    int wm = warp & 1, wn = warp >> 1;     // 2 x 4 warp grid

    int bid = blockIdx.x;
    int g = bid >> 6;                      // 0..5 = f*2 + type
    int mi = (bid >> 3) & 7;
    int nj = bid & 7;
    int f = g >> 1, type = g & 1;

    const __nv_bfloat16* Asrc = g_bi + (size_t)f * B * CD + (size_t)mi * 128 * 512;
    const __nv_bfloat16* Bsrc = (type ? g_bi : g_bj) + (size_t)f * B * CD + (size_t)nj * 128 * 512;

    auto issue_slab = [&](int stage, int ks) {
        uint32_t s = sb + stage * STAGE_BYTES;
#pragma unroll
        for (int q = 0; q < 4; q++) {
            int idx = tid + q * 256;           // 0..1023
            int r = idx >> 3;                  // row 0..127
            int kc = (idx & 7) * 8;            // col halves 0..56
            cpasync16(s + (r * PITCH + kc) * 2, Asrc + (size_t)r * 512 + ks + kc);
            cpasync16(s + TILE_BYTES + (r * PITCH + kc) * 2,
                      Bsrc + (size_t)r * 512 + ks + kc);
        }
    };

    float acc[4][4][4];
#pragma unroll
    for (int a = 0; a < 4; a++)
#pragma unroll
        for (int b = 0; b < 4; b++)
#pragma unroll
            for (int q = 0; q < 4; q++) acc[a][b][q] = 0.f;

    issue_slab(0, 0);
    CP_COMMIT();
    issue_slab(1, KSLAB);
    CP_COMMIT();

    for (int s = 0; s < 8; s++) {
        CP_WAIT1();
        __syncthreads();
        if (s + 2 < 8) issue_slab((s + 2) % 3, (s + 2) * KSLAB);
        CP_COMMIT();                       // uniform group count (may be empty)

        uint32_t base = sb + (s % 3) * STAGE_BYTES;
#pragma unroll
        for (int kt = 0; kt < 4; kt++) {
            uint32_t af[4][4], bfr[2][4];
#pragma unroll
            for (int mt = 0; mt < 4; mt++) {
                int row = wm * 64 + mt * 16 + ((lane >> 3) & 1) * 8 + (lane & 7);
                int col = kt * 16 + (lane >> 4) * 8;
                ldsm4(af[mt], base + (row * PITCH + col) * 2);
            }
#pragma unroll
            for (int nt2 = 0; nt2 < 2; nt2++) {
                int nrow = wn * 32 + nt2 * 16 + (lane >> 4) * 8 + (lane & 7);
                int kcol = kt * 16 + ((lane >> 3) & 1) * 8;
                ldsm4(bfr[nt2], base + TILE_BYTES + (nrow * PITCH + kcol) * 2);
            }
#pragma unroll
            for (int mt = 0; mt < 4; mt++)
#pragma unroll
                for (int nt = 0; nt < 4; nt++)
                    mma16816(acc[mt][nt], af[mt],
                             bfr[nt >> 1][(nt & 1) * 2], bfr[nt >> 1][(nt & 1) * 2 + 1]);
        }
    }

    // ---- fused epilogue ----
    __syncthreads();                       // all compute done; reuse pipeline smem
    float* sf = reinterpret_cast<float*>(smem);
    int gq = lane >> 2, tq = lane & 3;
#pragma unroll
    for (int mt = 0; mt < 4; mt++) {
#pragma unroll
        for (int nt = 0; nt < 4; nt++) {
            int m0 = wm * 64 + mt * 16 + gq;
            int n0 = wn * 32 + nt * 8 + tq * 2;
            *reinterpret_cast<float2*>(sf + m0 * EPITCH + n0) =
                make_float2(acc[mt][nt][0], acc[mt][nt][1]);
            *reinterpret_cast<float2*>(sf + (m0 + 8) * EPITCH + n0) =
                make_float2(acc[mt][nt][2], acc[mt][nt][3]);
        }
    }

    // batch-prefetch gather indices + norms (MLP 8; latency hides under the
    // dump/syncthreads). acc registers are dead by here.
    const int* idx = type ? idxk : idxj;
    const float* rn = type ? g_rni : g_rnj;
    int ccq[8];
    float rnq[8];
    if (lane < 16) {
#pragma unroll
        for (int q = 0; q < 8; q++) {
            int p = warp * 8 + q;
            int i = mi * 8 + (p >> 3), j = nj * 8 + (p & 7);
            ccq[q] = idx[((size_t)((f * B + i) * B) + j) * C + lane];
        }
#pragma unroll
        for (int q = 0; q < 8; q++) {
            int j = nj * 8 + ((warp * 8 + q) & 7);
            rnq[q] = rn[(f * B + j) * C + ccq[q]];
        }
    }
    bool is64 = (ids_raw[1] == 0) && (ids_raw[3] == 0) && (ids_raw[5] == 0) && (ids_raw[7] == 0);
    const long long* ids64 = reinterpret_cast<const long long*>(ids_raw);
    __syncthreads();

#pragma unroll
    for (int q = 0; q < 8; q++) {
        int p = warp * 8 + q;              // 0..63
        int il = p >> 3, jl = p & 7;
        int i = mi * 8 + il, j = nj * 8 + jl;
        float sacc = 0.f, nsq = 0.f;
        if (lane < 16) {
            sacc = sf[(il * 16 + lane) * EPITCH + jl * 16 + ccq[q]];
            nsq  = rnq[q];
        }
#pragma unroll
        for (int o = 8; o; o >>= 1) {
            sacc += __shfl_down_sync(0xffffffffu, sacc, o);
            nsq  += __shfl_down_sync(0xffffffffu, nsq, o);
        }
        if (lane == 0) {
            long long myid = is64 ? ids64[i] : (long long)ids_raw[i];
            long long jid  = is64 ? ids64[j] : (long long)ids_raw[j];
            float na = fmaxf(g_an[f * B + i], EPSF);
            float nb = fmaxf(sqrtf(nsq), EPSF);
            bool valid = (j != i) && (jid != myid);
            g_sim[(size_t)type * F * B * B + (size_t)(f * B + i) * B + j] =
                valid ? (sacc / (na * nb) * INV_T) : NEGINF;
        }
    }
}

// ---------------------------------------------------------------------------
// Kernel 3: logsumexp (one warp per row) + last-block final sum.
// grid = 6 blocks of 1024 threads (32 warps -> 32 rows each).
// ---------------------------------------------------------------------------
__global__ void __launch_bounds__(1024) k_lse(float* __restrict__ out) {
    int t = threadIdx.x, w = t >> 5, lane = t & 31;
    int r = blockIdx.x * 32 + w;            // 0..191
    __shared__ float ssum[32];
    __shared__ int s_last;

    float p = g_pos[r];
    const float* sj = g_sim + (size_t)r * B;
    const float* sk = g_sim + (size_t)F * B * B + (size_t)r * B;
    float v0 = sj[lane], v1 = sj[lane + 32], v2 = sk[lane], v3 = sk[lane + 32];
    float m = fmaxf(fmaxf(v0, v1), fmaxf(v2, v3));
    m = fmaxf(m, p);
    m = warpmax(m);
    float s = expf(v0 - m) + expf(v1 - m) + expf(v2 - m) + expf(v3 - m);
    s = warpsum(s);
    if (!lane) {
        g_loss[r] = logf(s + expf(p - m)) + m - p;
        __threadfence();                    // release this row's result
    }
    __syncthreads();
    if (t == 0) {
        int done = atomicAdd(&g_done, 1);
        s_last = (done == 5) ? 1 : 0;
    }
    __syncthreads();

    if (s_last) {
        __threadfence();                    // acquire all g_loss writes
        float v = (t < F * B) ? g_loss[t] : 0.f;
        v = warpsum(v);
        if (!lane) ssum[w] = v;
        __syncthreads();
        if (t == 0) {
            float tot = 0.f;
#pragma unroll
            for (int w2 = 0; w2 < 32; w2++) tot += ssum[w2];
            out[0] = tot * (1.0f / 128.0f);   // / (2 * BATCH_SIZE)
        }
    }
}

}  // namespace

extern "C" void kernel_launch(void* const* d_in, const int* in_sizes, int n_in,
                              void* d_out, int out_size) {
    const float* fi   = (const float*)d_in[0];
    const float* fj   = (const float*)d_in[1];
    const int*   ids  = (const int*)d_in[2];
    const int*   idxj = (const int*)d_in[3];
    const int*   idxk = (const int*)d_in[4];
    float* out = (float*)d_out;

    static bool attr_done = false;
    if (!attr_done) {
        cudaFuncSetAttribute(k_gram_mma, cudaFuncAttributeMaxDynamicSharedMemorySize,
                             GRAM_SMEM);
        attr_done = true;
    }

    k_prep<<<F * B, 1024>>>(fi, fj);
    k_gram_mma<<<6 * 64, 256, GRAM_SMEM>>>(ids, idxj, idxk);
    k_lse<<<6, 1024>>>(out);
}

// round 14
// speedup vs baseline: 1.0965x; 1.0459x over previous
#include <cuda_runtime.h>
#include <cuda_bf16.h>
#include <cstdint>
#include <math.h>

namespace {

constexpr int F = 3, B = 64, C = 16, D = 512;
constexpr int CD = C * D;                 // 8192
constexpr float EPSF = 1e-8f;
constexpr float NEGINF = -1e30f;
constexpr float INV_T = 10.0f;            // 1 / 0.1

// ---- device scratch (no allocation allowed) ----
__device__ __align__(16) __nv_bfloat16 g_bi[F * B * CD];   // bf16 fmaps_i
__device__ __align__(16) __nv_bfloat16 g_bj[F * B * CD];   // bf16 fmaps_j
__device__ __align__(16) float g_rni[F * B * C];  // per-channel ||.||^2 fmaps_i
__device__ __align__(16) float g_rnj[F * B * C];  // per-channel ||.||^2 fmaps_j
__device__ float g_an[F * B];             // anchor norms
__device__ float g_pos[F * B];            // pos_sim / T
__device__ float g_sim[2 * F * B * B];    // [type][f][i][j] logits
__device__ float g_loss[F * B];
__device__ int   g_done;                  // last-block counter (reset by k_prep)

__device__ __forceinline__ float warpsum(float v) {
#pragma unroll
    for (int o = 16; o; o >>= 1) v += __shfl_down_sync(0xffffffffu, v, o);
    return v;
}
__device__ __forceinline__ float warpmax(float v) {
#pragma unroll
    for (int o = 16; o; o >>= 1) v = fmaxf(v, __shfl_xor_sync(0xffffffffu, v, o));
    return v;
}

__device__ __forceinline__ uint32_t smem_u32(const void* p) {
    uint32_t a;
    asm("{ .reg .u64 t; cvta.to.shared.u64 t, %1; cvt.u32.u64 %0, t; }" : "=r"(a) : "l"(p));
    return a;
}
__device__ __forceinline__ void ldsm4(uint32_t* r, uint32_t addr) {
    asm volatile("ldmatrix.sync.aligned.m8n8.x4.shared.b16 {%0,%1,%2,%3}, [%4];"
        : "=r"(r[0]), "=r"(r[1]), "=r"(r[2]), "=r"(r[3]) : "r"(addr));
}
__device__ __forceinline__ void mma16816(float* c, const uint32_t* a,
                                         uint32_t b0, uint32_t b1) {
    asm volatile(
        "mma.sync.aligned.m16n8k16.row.col.f32.bf16.bf16.f32 "
        "{%0,%1,%2,%3}, {%4,%5,%6,%7}, {%8,%9}, {%0,%1,%2,%3};"
        : "+f"(c[0]), "+f"(c[1]), "+f"(c[2]), "+f"(c[3])
        : "r"(a[0]), "r"(a[1]), "r"(a[2]), "r"(a[3]), "r"(b0), "r"(b1));
}
__device__ __forceinline__ void cpasync16(uint32_t dst, const void* src) {
    asm volatile("cp.async.cg.shared.global [%0], [%1], 16;" :: "r"(dst), "l"(src));
}
#define CP_COMMIT() asm volatile("cp.async.commit_group;" ::: "memory")
#define CP_WAIT1() asm volatile("cp.async.wait_group 1;" ::: "memory")
#define CP_WAIT0() asm volatile("cp.async.wait_group 0;" ::: "memory")

// ---------------------------------------------------------------------------
// Kernel 1: fused prep — one pass over fp32 inputs, 1024 threads/block.
// ---------------------------------------------------------------------------
__global__ void __launch_bounds__(1024) k_prep(const float* __restrict__ fi,
                                               const float* __restrict__ fj) {
    int fb = blockIdx.x;
    int t = threadIdx.x, w = t >> 5, lane = t & 31;
    if (fb == 0 && t == 0) g_done = 0;
    int ch = w >> 1, half = w & 1;
    const float4* ai = reinterpret_cast<const float4*>(fi + (size_t)fb * CD);
    const float4* aj = reinterpret_cast<const float4*>(fj + (size_t)fb * CD);
    __nv_bfloat162* bi = reinterpret_cast<__nv_bfloat162*>(g_bi + (size_t)fb * CD);
    __nv_bfloat162* bj = reinterpret_cast<__nv_bfloat162*>(g_bj + (size_t)fb * CD);

    __shared__ float sni[32], snj[32], sdot[32];

    float ssi = 0.f, ssj = 0.f, dot = 0.f;
#pragma unroll
    for (int q = 0; q < 2; q++) {
        int k = ch * 128 + half * 64 + q * 32 + lane;   // float4 index
        float4 vi = ai[k], vj = aj[k];
        ssi += vi.x * vi.x + vi.y * vi.y + vi.z * vi.z + vi.w * vi.w;
        ssj += vj.x * vj.x + vj.y * vj.y + vj.z * vj.z + vj.w * vj.w;
        dot += vi.x * vj.x + vi.y * vj.y + vi.z * vj.z + vi.w * vj.w;
        bi[2 * k]     = __floats2bfloat162_rn(vi.x, vi.y);
        bi[2 * k + 1] = __floats2bfloat162_rn(vi.z, vi.w);
        bj[2 * k]     = __floats2bfloat162_rn(vj.x, vj.y);
        bj[2 * k + 1] = __floats2bfloat162_rn(vj.z, vj.w);
    }
    ssi = warpsum(ssi);
    ssj = warpsum(ssj);
    dot = warpsum(dot);
    if (!lane) { sni[w] = ssi; snj[w] = ssj; sdot[w] = dot; }
    __syncthreads();
    if (t < C) {
        g_rni[fb * C + t] = sni[2 * t] + sni[2 * t + 1];
        g_rnj[fb * C + t] = snj[2 * t] + snj[2 * t + 1];
    }
    if (t == 0) {
        float na2 = 0.f, nb2 = 0.f, td = 0.f;
#pragma unroll
        for (int w2 = 0; w2 < 32; w2++) { na2 += sni[w2]; nb2 += snj[w2]; td += sdot[w2]; }
        float na = sqrtf(na2), nb = sqrtf(nb2);
        g_an[fb]  = na;
        g_pos[fb] = td / (fmaxf(na, EPSF) * fmaxf(nb, EPSF)) * INV_T;
    }
}

// ---------------------------------------------------------------------------
// Kernel 2: channel Gram via mma.sync (3-stage cp.async, K-slab 64) with a
// REGISTER-FREE fused epilogue: gather indices + norm rows are cp.async'd
// into smem scratch (no register arrays -> no spill under the
// launch_bounds(256,2) reg cap, which is the R10/R12 regression theory),
// ids + anchor norms preloaded into static smem. 128x128 fp32 tile -> smem,
// each 16x16 sub-block yields one gathered-negative logit -> g_sim.
// ---------------------------------------------------------------------------
constexpr int KSLAB = 64;
constexpr int PITCH = 72;                    // halves per smem row (64 + 8 pad)
constexpr int TILE_BYTES = 128 * PITCH * 2;  // 18432 B
constexpr int STAGE_BYTES = 2 * TILE_BYTES;  // 36864 B (A + B)
constexpr int GRAM_SMEM = 3 * STAGE_BYTES;   // 110592 B
constexpr int EPITCH = 132;                  // fp32 epilogue pitch (128 + 4)
constexpr int SCR_IDX = 128 * EPITCH * 4;    // 67584: idx tile (64*16 ints)
constexpr int SCR_NRM = SCR_IDX + 4096;      // 71680: norm rows (8*16 floats)

__global__ void __launch_bounds__(256, 2) k_gram_mma(const int* __restrict__ ids_raw,
                                                     const int* __restrict__ idxj,
                                                     const int* __restrict__ idxk) {
    extern __shared__ __align__(16) char smem[];
    __shared__ long long s_ids[B];           // static: batch ids
    __shared__ float s_an[8];                // static: anchor norms for this mi
    uint32_t sb = smem_u32(smem);
    int tid = threadIdx.x, lane = tid & 31, warp = tid >> 5;
    int wm = warp & 1, wn = warp >> 1;       // 2 x 4 warp grid

    int bid = blockIdx.x;
    int g = bid >> 6;                        // 0..5 = f*2 + type
    int mi = (bid >> 3) & 7;
    int nj = bid & 7;
    int f = g >> 1, type = g & 1;

    // preload ids + anchor norms into static smem (latency hides under slab 0)
    bool is64 = (ids_raw[1] == 0) && (ids_raw[3] == 0) && (ids_raw[5] == 0) && (ids_raw[7] == 0);
    if (tid < B) {
        s_ids[tid] = is64 ? reinterpret_cast<const long long*>(ids_raw)[tid]
                          : (long long)ids_raw[tid];
    }
    if (tid >= B && tid < B + 8) s_an[tid - B] = g_an[f * B + mi * 8 + (tid - B)];

    const __nv_bfloat16* Asrc = g_bi + (size_t)f * B * CD + (size_t)mi * 128 * 512;
    const __nv_bfloat16* Bsrc = (type ? g_bi : g_bj) + (size_t)f * B * CD + (size_t)nj * 128 * 512;

    auto issue_slab = [&](int stage, int ks) {
        uint32_t s = sb + stage * STAGE_BYTES;
#pragma unroll
        for (int q = 0; q < 4; q++) {
            int idx = tid + q * 256;           // 0..1023
            int r = idx >> 3;                  // row 0..127
            int kc = (idx & 7) * 8;            // col halves 0..56
            cpasync16(s + (r * PITCH + kc) * 2, Asrc + (size_t)r * 512 + ks + kc);
            cpasync16(s + TILE_BYTES + (r * PITCH + kc) * 2,
                      Bsrc + (size_t)r * 512 + ks + kc);
        }
    };

    float acc[4][4][4];
#pragma unroll
    for (int a = 0; a < 4; a++)
#pragma unroll
        for (int b = 0; b < 4; b++)
#pragma unroll
            for (int q = 0; q < 4; q++) acc[a][b][q] = 0.f;

    issue_slab(0, 0);
    CP_COMMIT();
    issue_slab(1, KSLAB);
    CP_COMMIT();

    for (int s = 0; s < 8; s++) {
        CP_WAIT1();
        __syncthreads();
        if (s + 2 < 8) issue_slab((s + 2) % 3, (s + 2) * KSLAB);
        CP_COMMIT();                       // uniform group count (may be empty)

        uint32_t base = sb + (s % 3) * STAGE_BYTES;
#pragma unroll
        for (int kt = 0; kt < 4; kt++) {
            uint32_t af[4][4], bfr[2][4];
#pragma unroll
            for (int mt = 0; mt < 4; mt++) {
                int row = wm * 64 + mt * 16 + ((lane >> 3) & 1) * 8 + (lane & 7);
                int col = kt * 16 + (lane >> 4) * 8;
                ldsm4(af[mt], base + (row * PITCH + col) * 2);
            }
#pragma unroll
            for (int nt2 = 0; nt2 < 2; nt2++) {
                int nrow = wn * 32 + nt2 * 16 + (lane >> 4) * 8 + (lane & 7);
                int kcol = kt * 16 + ((lane >> 3) & 1) * 8;
                ldsm4(bfr[nt2], base + TILE_BYTES + (nrow * PITCH + kcol) * 2);
            }
#pragma unroll
            for (int mt = 0; mt < 4; mt++)
#pragma unroll
                for (int nt = 0; nt < 4; nt++)
                    mma16816(acc[mt][nt], af[mt],
                             bfr[nt >> 1][(nt & 1) * 2], bfr[nt >> 1][(nt & 1) * 2 + 1]);
        }
    }

    // ---- fused epilogue (register-free staging) ----
    __syncthreads();                       // all compute done; reuse pipeline smem

    // stage gather metadata into smem scratch via cp.async (zero registers).
    {
        const int* idx = type ? idxk : idxj;
        const float* rn = type ? g_rni : g_rnj;
        int il = tid >> 5, jl = (tid >> 2) & 7, seg = tid & 3;
        cpasync16(sb + SCR_IDX + (((il * 8 + jl) * 16 + seg * 4) << 2),
                  idx + ((size_t)((f * B + mi * 8 + il) * B) + nj * 8 + jl) * C + seg * 4);
        if (tid < 32) {
            cpasync16(sb + SCR_NRM + (((tid >> 2) * 16 + (tid & 3) * 4) << 2),
                      rn + (f * B + nj * 8 + (tid >> 2)) * C + (tid & 3) * 4);
        }
        CP_COMMIT();
    }

    // dump accumulators (overlaps the scratch cp.async)
    float* sf = reinterpret_cast<float*>(smem);
    int gq = lane >> 2, tq = lane & 3;
#pragma unroll
    for (int mt = 0; mt < 4; mt++) {
#pragma unroll
        for (int nt = 0; nt < 4; nt++) {
            int m0 = wm * 64 + mt * 16 + gq;
            int n0 = wn * 32 + nt * 8 + tq * 2;
            *reinterpret_cast<float2*>(sf + m0 * EPITCH + n0) =
                make_float2(acc[mt][nt][0], acc[mt][nt][1]);
            *reinterpret_cast<float2*>(sf + (m0 + 8) * EPITCH + n0) =
                make_float2(acc[mt][nt][2], acc[mt][nt][3]);
        }
    }
    CP_WAIT0();
    __syncthreads();

    const int* sidx = reinterpret_cast<const int*>(smem + SCR_IDX);
    const float* snrm = reinterpret_cast<const float*>(smem + SCR_NRM);

#pragma unroll
    for (int q = 0; q < 8; q++) {
        int p = warp * 8 + q;              // 0..63
        int il = p >> 3, jl = p & 7;
        float sacc = 0.f, nsq = 0.f;
        if (lane < 16) {
            int cc = sidx[(il * 8 + jl) * 16 + lane];
            sacc = sf[(il * 16 + lane) * EPITCH + jl * 16 + cc];
            nsq  = snrm[jl * 16 + cc];
        }
#pragma unroll
        for (int o = 8; o; o >>= 1) {
            sacc += __shfl_down_sync(0xffffffffu, sacc, o);
            nsq  += __shfl_down_sync(0xffffffffu, nsq, o);
        }
        if (lane == 0) {
            int i = mi * 8 + il, j = nj * 8 + jl;
            float na = fmaxf(s_an[il], EPSF);
            float nb = fmaxf(sqrtf(nsq), EPSF);
            bool valid = (j != i) && (s_ids[j] != s_ids[i]);
            g_sim[(size_t)type * F * B * B + (size_t)(f * B + i) * B + j] =
                valid ? (sacc / (na * nb) * INV_T) : NEGINF;
        }
    }
}

// ---------------------------------------------------------------------------
// Kernel 3: logsumexp (one warp per row) + last-block final sum.
// grid = 6 blocks of 1024 threads (32 warps -> 32 rows each).
// ---------------------------------------------------------------------------
__global__ void __launch_bounds__(1024) k_lse(float* __restrict__ out) {
    int t = threadIdx.x, w = t >> 5, lane = t & 31;
    int r = blockIdx.x * 32 + w;            // 0..191
    __shared__ float ssum[32];
    __shared__ int s_last;

    float p = g_pos[r];
    const float* sj = g_sim + (size_t)r * B;
    const float* sk = g_sim + (size_t)F * B * B + (size_t)r * B;
    float v0 = sj[lane], v1 = sj[lane + 32], v2 = sk[lane], v3 = sk[lane + 32];
    float m = fmaxf(fmaxf(v0, v1), fmaxf(v2, v3));
    m = fmaxf(m, p);
    m = warpmax(m);
    float s = expf(v0 - m) + expf(v1 - m) + expf(v2 - m) + expf(v3 - m);
    s = warpsum(s);
    if (!lane) {
        g_loss[r] = logf(s + expf(p - m)) + m - p;
        __threadfence();                    // release this row's result
    }
    __syncthreads();
    if (t == 0) {
        int done = atomicAdd(&g_done, 1);
        s_last = (done == 5) ? 1 : 0;
    }
    __syncthreads();

    if (s_last) {
        __threadfence();                    // acquire all g_loss writes
        float v = (t < F * B) ? g_loss[t] : 0.f;
        v = warpsum(v);
        if (!lane) ssum[w] = v;
        __syncthreads();
        if (t == 0) {
            float tot = 0.f;
#pragma unroll
            for (int w2 = 0; w2 < 32; w2++) tot += ssum[w2];
            out[0] = tot * (1.0f / 128.0f);   // / (2 * BATCH_SIZE)
        }
    }
}

}  // namespace

extern "C" void kernel_launch(void* const* d_in, const int* in_sizes, int n_in,
                              void* d_out, int out_size) {
    const float* fi   = (const float*)d_in[0];
    const float* fj   = (const float*)d_in[1];
    const int*   ids  = (const int*)d_in[2];
    const int*   idxj = (const int*)d_in[3];
    const int*   idxk = (const int*)d_in[4];
    float* out = (float*)d_out;

    static bool attr_done = false;
    if (!attr_done) {
        cudaFuncSetAttribute(k_gram_mma, cudaFuncAttributeMaxDynamicSharedMemorySize,
                             GRAM_SMEM);
        attr_done = true;
    }

    k_prep<<<F * B, 1024>>>(fi, fj);
    k_gram_mma<<<6 * 64, 256, GRAM_SMEM>>>(ids, idxj, idxk);
    k_lse<<<6, 1024>>>(out);
}

// round 16
// speedup vs baseline: 1.1008x; 1.0039x over previous
#include <cuda_runtime.h>
#include <cuda_bf16.h>
#include <cstdint>
#include <math.h>

namespace {

constexpr int F = 3, B = 64, C = 16, D = 512;
constexpr int CD = C * D;                 // 8192
constexpr float EPSF = 1e-8f;
constexpr float NEGINF = -1e30f;
constexpr float INV_T = 10.0f;            // 1 / 0.1

// ---- device scratch (no allocation allowed) ----
__device__ __align__(16) __nv_bfloat16 g_bi[F * B * CD];   // bf16 fmaps_i
__device__ __align__(16) __nv_bfloat16 g_bj[F * B * CD];   // bf16 fmaps_j
__device__ __align__(16) float g_rni[F * B * C];  // per-channel ||.||^2 fmaps_i
__device__ __align__(16) float g_rnj[F * B * C];  // per-channel ||.||^2 fmaps_j
__device__ __align__(16) float g_pp[F * B * 8];   // partials: {dot0,dot1,ni0,ni1,nj0,nj1,-,-}
__device__ float g_sim[2 * F * B * B];    // [type][f][i][j] logits
__device__ float g_loss[F * B];
__device__ int   g_done;                  // last-block counter (reset by k_prep)

__device__ __forceinline__ float warpsum(float v) {
#pragma unroll
    for (int o = 16; o; o >>= 1) v += __shfl_down_sync(0xffffffffu, v, o);
    return v;
}
__device__ __forceinline__ float warpmax(float v) {
#pragma unroll
    for (int o = 16; o; o >>= 1) v = fmaxf(v, __shfl_xor_sync(0xffffffffu, v, o));
    return v;
}

__device__ __forceinline__ uint32_t smem_u32(const void* p) {
    uint32_t a;
    asm("{ .reg .u64 t; cvta.to.shared.u64 t, %1; cvt.u32.u64 %0, t; }" : "=r"(a) : "l"(p));
    return a;
}
__device__ __forceinline__ void ldsm4(uint32_t* r, uint32_t addr) {
    asm volatile("ldmatrix.sync.aligned.m8n8.x4.shared.b16 {%0,%1,%2,%3}, [%4];"
        : "=r"(r[0]), "=r"(r[1]), "=r"(r[2]), "=r"(r[3]) : "r"(addr));
}
__device__ __forceinline__ void mma16816(float* c, const uint32_t* a,
                                         uint32_t b0, uint32_t b1) {
    asm volatile(
        "mma.sync.aligned.m16n8k16.row.col.f32.bf16.bf16.f32 "
        "{%0,%1,%2,%3}, {%4,%5,%6,%7}, {%8,%9}, {%0,%1,%2,%3};"
        : "+f"(c[0]), "+f"(c[1]), "+f"(c[2]), "+f"(c[3])
        : "r"(a[0]), "r"(a[1]), "r"(a[2]), "r"(a[3]), "r"(b0), "r"(b1));
}
__device__ __forceinline__ void cpasync16(uint32_t dst, const void* src) {
    asm volatile("cp.async.cg.shared.global [%0], [%1], 16;" :: "r"(dst), "l"(src));
}
#define CP_COMMIT() asm volatile("cp.async.commit_group;" ::: "memory")
#define CP_WAIT1() asm volatile("cp.async.wait_group 1;" ::: "memory")
#define CP_WAIT0() asm volatile("cp.async.wait_group 0;" ::: "memory")

// ---------------------------------------------------------------------------
// Kernel 1: prep, 2 CTAs per (f,b) row — grid 384 x 512 threads.
// CTA (fb, half) owns channels [half*8, half*8+8): bf16 convert + channel
// norms (CTA-local) + PARTIAL row dot/norms -> g_pp (summed downstream in
// fixed order; no float atomics, stays deterministic).
// ---------------------------------------------------------------------------
__global__ void __launch_bounds__(512) k_prep(const float* __restrict__ fi,
                                              const float* __restrict__ fj) {
    int bid = blockIdx.x;
    int fb = bid >> 1, half = bid & 1;
    int t = threadIdx.x, w = t >> 5, lane = t & 31;
    if (bid == 0 && t == 0) g_done = 0;
    int ch = half * 8 + (w >> 1);          // channel 0..15
    int hh = w & 1;                        // half-channel
    const float4* ai = reinterpret_cast<const float4*>(fi + (size_t)fb * CD);
    const float4* aj = reinterpret_cast<const float4*>(fj + (size_t)fb * CD);
    __nv_bfloat162* bi = reinterpret_cast<__nv_bfloat162*>(g_bi + (size_t)fb * CD);
    __nv_bfloat162* bj = reinterpret_cast<__nv_bfloat162*>(g_bj + (size_t)fb * CD);

    __shared__ float sni[16], snj[16], sdot[16];

    float ssi = 0.f, ssj = 0.f, dot = 0.f;
#pragma unroll
    for (int q = 0; q < 2; q++) {
        int k = ch * 128 + hh * 64 + q * 32 + lane;   // float4 index
        float4 vi = ai[k], vj = aj[k];
        ssi += vi.x * vi.x + vi.y * vi.y + vi.z * vi.z + vi.w * vi.w;
        ssj += vj.x * vj.x + vj.y * vj.y + vj.z * vj.z + vj.w * vj.w;
        dot += vi.x * vj.x + vi.y * vj.y + vi.z * vj.z + vi.w * vj.w;
        bi[2 * k]     = __floats2bfloat162_rn(vi.x, vi.y);
        bi[2 * k + 1] = __floats2bfloat162_rn(vi.z, vi.w);
        bj[2 * k]     = __floats2bfloat162_rn(vj.x, vj.y);
        bj[2 * k + 1] = __floats2bfloat162_rn(vj.z, vj.w);
    }
    ssi = warpsum(ssi);
    ssj = warpsum(ssj);
    dot = warpsum(dot);
    if (!lane) { sni[w] = ssi; snj[w] = ssj; sdot[w] = dot; }
    __syncthreads();
    if (t < 8) {
        g_rni[fb * C + half * 8 + t] = sni[2 * t] + sni[2 * t + 1];
        g_rnj[fb * C + half * 8 + t] = snj[2 * t] + snj[2 * t + 1];
    }
    if (t == 0) {
        float ni = 0.f, nj2 = 0.f, td = 0.f;
#pragma unroll
        for (int w2 = 0; w2 < 16; w2++) { ni += sni[w2]; nj2 += snj[w2]; td += sdot[w2]; }
        g_pp[fb * 8 + 0 + half] = td;
        g_pp[fb * 8 + 2 + half] = ni;
        g_pp[fb * 8 + 4 + half] = nj2;
    }
}

// ---------------------------------------------------------------------------
// Kernel 2: channel Gram via mma.sync (3-stage cp.async, K-slab 64) with the
// register-free fused epilogue (R14-passing): gather indices + norm rows are
// cp.async'd into smem scratch; ids + anchor norms (from g_pp partials) in
// static smem. 128x128 fp32 tile -> smem, each 16x16 sub-block yields one
// gathered-negative logit -> g_sim.
// ---------------------------------------------------------------------------
constexpr int KSLAB = 64;
constexpr int PITCH = 72;                    // halves per smem row (64 + 8 pad)
constexpr int TILE_BYTES = 128 * PITCH * 2;  // 18432 B
constexpr int STAGE_BYTES = 2 * TILE_BYTES;  // 36864 B (A + B)
constexpr int GRAM_SMEM = 3 * STAGE_BYTES;   // 110592 B
constexpr int EPITCH = 132;                  // fp32 epilogue pitch (128 + 4)
constexpr int SCR_IDX = 128 * EPITCH * 4;    // 67584: idx tile (64*16 ints)
constexpr int SCR_NRM = SCR_IDX + 4096;      // 71680: norm rows (8*16 floats)

__global__ void __launch_bounds__(256, 2) k_gram_mma(const int* __restrict__ ids_raw,
                                                     const int* __restrict__ idxj,
                                                     const int* __restrict__ idxk) {
    extern __shared__ __align__(16) char smem[];
    __shared__ long long s_ids[B];           // static: batch ids
    __shared__ float s_an[8];                // static: anchor norms for this mi
    uint32_t sb = smem_u32(smem);
    int tid = threadIdx.x, lane = tid & 31, warp = tid >> 5;
    int wm = warp & 1, wn = warp >> 1;       // 2 x 4 warp grid

    int bid = blockIdx.x;
    int g = bid >> 6;                        // 0..5 = f*2 + type
    int mi = (bid >> 3) & 7;
    int nj = bid & 7;
    int f = g >> 1, type = g & 1;

    // preload ids + anchor norms into static smem (latency hides under slab 0)
    bool is64 = (ids_raw[1] == 0) && (ids_raw[3] == 0) && (ids_raw[5] == 0) && (ids_raw[7] == 0);
    if (tid < B) {
        s_ids[tid] = is64 ? reinterpret_cast<const long long*>(ids_raw)[tid]
                          : (long long)ids_raw[tid];
    }
    if (tid >= B && tid < B + 8) {
        int row = f * B + mi * 8 + (tid - B);
        s_an[tid - B] = sqrtf(g_pp[row * 8 + 2] + g_pp[row * 8 + 3]);
    }

    const __nv_bfloat16* Asrc = g_bi + (size_t)f * B * CD + (size_t)mi * 128 * 512;
    const __nv_bfloat16* Bsrc = (type ? g_bi : g_bj) + (size_t)f * B * CD + (size_t)nj * 128 * 512;

    auto issue_slab = [&](int stage, int ks) {
        uint32_t s = sb + stage * STAGE_BYTES;
#pragma unroll
        for (int q = 0; q < 4; q++) {
            int idx = tid + q * 256;           // 0..1023
            int r = idx >> 3;                  // row 0..127
            int kc = (idx & 7) * 8;            // col halves 0..56
            cpasync16(s + (r * PITCH + kc) * 2, Asrc + (size_t)r * 512 + ks + kc);
            cpasync16(s + TILE_BYTES + (r * PITCH + kc) * 2,
                      Bsrc + (size_t)r * 512 + ks + kc);
        }
    };

    float acc[4][4][4];
#pragma unroll
    for (int a = 0; a < 4; a++)
#pragma unroll
        for (int b = 0; b < 4; b++)
#pragma unroll
            for (int q = 0; q < 4; q++) acc[a][b][q] = 0.f;

    issue_slab(0, 0);
    CP_COMMIT();
    issue_slab(1, KSLAB);
    CP_COMMIT();

    for (int s = 0; s < 8; s++) {
        CP_WAIT1();
        __syncthreads();
        if (s + 2 < 8) issue_slab((s + 2) % 3, (s + 2) * KSLAB);
        CP_COMMIT();                       // uniform group count (may be empty)

        uint32_t base = sb + (s % 3) * STAGE_BYTES;
#pragma unroll
        for (int kt = 0; kt < 4; kt++) {
            uint32_t af[4][4], bfr[2][4];
#pragma unroll
            for (int mt = 0; mt < 4; mt++) {
                int row = wm * 64 + mt * 16 + ((lane >> 3) & 1) * 8 + (lane & 7);
                int col = kt * 16 + (lane >> 4) * 8;
                ldsm4(af[mt], base + (row * PITCH + col) * 2);
            }
#pragma unroll
            for (int nt2 = 0; nt2 < 2; nt2++) {
                int nrow = wn * 32 + nt2 * 16 + (lane >> 4) * 8 + (lane & 7);
                int kcol = kt * 16 + ((lane >> 3) & 1) * 8;
                ldsm4(bfr[nt2], base + TILE_BYTES + (nrow * PITCH + kcol) * 2);
            }
#pragma unroll
            for (int mt = 0; mt < 4; mt++)
#pragma unroll
                for (int nt = 0; nt < 4; nt++)
                    mma16816(acc[mt][nt], af[mt],
                             bfr[nt >> 1][(nt & 1) * 2], bfr[nt >> 1][(nt & 1) * 2 + 1]);
        }
    }

    // ---- fused epilogue (register-free staging) ----
    __syncthreads();                       // all compute done; reuse pipeline smem

    // stage gather metadata into smem scratch via cp.async (zero registers).
    {
        const int* idx = type ? idxk : idxj;
        const float* rn = type ? g_rni : g_rnj;
        int il = tid >> 5, jl = (tid >> 2) & 7, seg = tid & 3;
        cpasync16(sb + SCR_IDX + (((il * 8 + jl) * 16 + seg * 4) << 2),
                  idx + ((size_t)((f * B + mi * 8 + il) * B) + nj * 8 + jl) * C + seg * 4);
        if (tid < 32) {
            cpasync16(sb + SCR_NRM + (((tid >> 2) * 16 + (tid & 3) * 4) << 2),
                      rn + (f * B + nj * 8 + (tid >> 2)) * C + (tid & 3) * 4);
        }
        CP_COMMIT();
    }

    // dump accumulators (overlaps the scratch cp.async)
    float* sf = reinterpret_cast<float*>(smem);
    int gq = lane >> 2, tq = lane & 3;
#pragma unroll
    for (int mt = 0; mt < 4; mt++) {
#pragma unroll
        for (int nt = 0; nt < 4; nt++) {
            int m0 = wm * 64 + mt * 16 + gq;
            int n0 = wn * 32 + nt * 8 + tq * 2;
            *reinterpret_cast<float2*>(sf + m0 * EPITCH + n0) =
                make_float2(acc[mt][nt][0], acc[mt][nt][1]);
            *reinterpret_cast<float2*>(sf + (m0 + 8) * EPITCH + n0) =
                make_float2(acc[mt][nt][2], acc[mt][nt][3]);
        }
    }
    CP_WAIT0();
    __syncthreads();

    const int* sidx = reinterpret_cast<const int*>(smem + SCR_IDX);
    const float* snrm = reinterpret_cast<const float*>(smem + SCR_NRM);

#pragma unroll
    for (int q = 0; q < 8; q++) {
        int p = warp * 8 + q;              // 0..63
        int il = p >> 3, jl = p & 7;
        float sacc = 0.f, nsq = 0.f;
        if (lane < 16) {
            int cc = sidx[(il * 8 + jl) * 16 + lane];
            sacc = sf[(il * 16 + lane) * EPITCH + jl * 16 + cc];
            nsq  = snrm[jl * 16 + cc];
        }
#pragma unroll
        for (int o = 8; o; o >>= 1) {
            sacc += __shfl_down_sync(0xffffffffu, sacc, o);
            nsq  += __shfl_down_sync(0xffffffffu, nsq, o);
        }
        if (lane == 0) {
            int i = mi * 8 + il, j = nj * 8 + jl;
            float na = fmaxf(s_an[il], EPSF);
            float nb = fmaxf(sqrtf(nsq), EPSF);
            bool valid = (j != i) && (s_ids[j] != s_ids[i]);
            g_sim[(size_t)type * F * B * B + (size_t)(f * B + i) * B + j] =
                valid ? (sacc / (na * nb) * INV_T) : NEGINF;
        }
    }
}

// ---------------------------------------------------------------------------
// Kernel 3: logsumexp (one warp per row) + last-block final sum.
// pos_sim reconstructed from g_pp partials (fixed-order sum, deterministic).
// grid = 6 blocks of 1024 threads (32 warps -> 32 rows each).
// ---------------------------------------------------------------------------
__global__ void __launch_bounds__(1024) k_lse(float* __restrict__ out) {
    int t = threadIdx.x, w = t >> 5, lane = t & 31;
    int r = blockIdx.x * 32 + w;            // 0..191
    __shared__ float ssum[32];
    __shared__ int s_last;

    float d  = g_pp[r * 8 + 0] + g_pp[r * 8 + 1];
    float na = sqrtf(g_pp[r * 8 + 2] + g_pp[r * 8 + 3]);
    float nb = sqrtf(g_pp[r * 8 + 4] + g_pp[r * 8 + 5]);
    float p  = d / (fmaxf(na, EPSF) * fmaxf(nb, EPSF)) * INV_T;

    const float* sj = g_sim + (size_t)r * B;
    const float* sk = g_sim + (size_t)F * B * B + (size_t)r * B;
    float v0 = sj[lane], v1 = sj[lane + 32], v2 = sk[lane], v3 = sk[lane + 32];
    float m = fmaxf(fmaxf(v0, v1), fmaxf(v2, v3));
    m = fmaxf(m, p);
    m = warpmax(m);
    float s = expf(v0 - m) + expf(v1 - m) + expf(v2 - m) + expf(v3 - m);
    s = warpsum(s);
    if (!lane) {
        g_loss[r] = logf(s + expf(p - m)) + m - p;
        __threadfence();                    // release this row's result
    }
    __syncthreads();
    if (t == 0) {
        int done = atomicAdd(&g_done, 1);
        s_last = (done == 5) ? 1 : 0;
    }
    __syncthreads();

    if (s_last) {
        __threadfence();                    // acquire all g_loss writes
        float v = (t < F * B) ? g_loss[t] : 0.f;
        v = warpsum(v);
        if (!lane) ssum[w] = v;
        __syncthreads();
        if (t == 0) {
            float tot = 0.f;
#pragma unroll
            for (int w2 = 0; w2 < 32; w2++) tot += ssum[w2];
            out[0] = tot * (1.0f / 128.0f);   // / (2 * BATCH_SIZE)
        }
    }
}

}  // namespace

extern "C" void kernel_launch(void* const* d_in, const int* in_sizes, int n_in,
                              void* d_out, int out_size) {
    const float* fi   = (const float*)d_in[0];
    const float* fj   = (const float*)d_in[1];
    const int*   ids  = (const int*)d_in[2];
    const int*   idxj = (const int*)d_in[3];
    const int*   idxk = (const int*)d_in[4];
    float* out = (float*)d_out;

    static bool attr_done = false;
    if (!attr_done) {
        cudaFuncSetAttribute(k_gram_mma, cudaFuncAttributeMaxDynamicSharedMemorySize,
                             GRAM_SMEM);
        attr_done = true;
    }

    k_prep<<<2 * F * B, 512>>>(fi, fj);
    k_gram_mma<<<6 * 64, 256, GRAM_SMEM>>>(ids, idxj, idxk);
    k_lse<<<6, 1024>>>(out);
}